// round 2
// baseline (speedup 1.0000x reference)
#include <cuda_runtime.h>
#include <cstdint>

#define T_STEPS 16384
#define H       512
#define DYN     16
#define S       32
#define XW      (DYN + S)

#define NCTA          128
#define WARPS_PER_CTA 4

// ---------------- static device scratch (allocation-free rule) ----------------
__device__ float g_hbuf[2][H];           // double-buffered hidden state
__device__ int   g_flags[H];             // per-dim completed-step stamp
__device__ float g_hall[(size_t)T_STEPS * H];   // 32 MB
__device__ float g_gi [(size_t)T_STEPS * H];    // sigmoid(input gate), 32 MB
__device__ float g_xf [(size_t)T_STEPS * H];
__device__ float g_xg [(size_t)T_STEPS * H];
__device__ float g_xo [(size_t)T_STEPS * H];

// ---------------- helpers ----------------
__device__ __forceinline__ float sigmoid_fast(float x) {
    return __fdividef(1.0f, 1.0f + __expf(-x));
}
__device__ __forceinline__ float tanh_fast(float x) {
    // symmetric form avoids inf/inf NaN for large |x|
    float ax = fabsf(x);
    float e  = __expf(-2.0f * ax);
    float r  = __fdividef(1.0f - e, 1.0f + e);
    return copysignf(r, x);
}
__device__ __forceinline__ int acq_load(const int* p) {
    int v;
    asm volatile("ld.global.acquire.gpu.b32 %0, [%1];" : "=r"(v) : "l"(p) : "memory");
    return v;
}
__device__ __forceinline__ void rel_store(int* p, int v) {
    asm volatile("st.global.release.gpu.b32 [%0], %1;" :: "l"(p), "r"(v) : "memory");
}
__device__ __forceinline__ void st_cg(float* p, float v) {
    asm volatile("st.global.cg.f32 [%0], %1;" :: "l"(p), "f"(v) : "memory");
}

// ---------------- init: reset state each launch (graph replay safe) ----------
__global__ void init_kernel(const float* __restrict__ h0) {
    int i = threadIdx.x;            // 512 threads
    g_hbuf[0][i] = h0[i];
    g_flags[i]   = 0;
}

// ---------------- prologue: gate pre-activations, parallel over T ------------
__global__ void __launch_bounds__(512) pre_kernel(
    const float* __restrict__ x,
    const float* __restrict__ Wi,  const float* __restrict__ bi,
    const float* __restrict__ Wf1, const float* __restrict__ bf1, const float* __restrict__ bf2,
    const float* __restrict__ Wg1, const float* __restrict__ bg1, const float* __restrict__ bg2,
    const float* __restrict__ Wo1, const float* __restrict__ bo1, const float* __restrict__ bo2)
{
    const int d = threadIdx.x;      // 512 threads = one h-dim each
    float wi[S], wf[DYN], wg[DYN], wo[DYN];
#pragma unroll
    for (int s = 0; s < S; s++)   wi[s] = __ldg(&Wi[d * S + s]);
#pragma unroll
    for (int k = 0; k < DYN; k++) {
        wf[k] = __ldg(&Wf1[d * DYN + k]);
        wg[k] = __ldg(&Wg1[d * DYN + k]);
        wo[k] = __ldg(&Wo1[d * DYN + k]);
    }
    const float b_i = __ldg(&bi[d]);
    const float b_f = __ldg(&bf1[d]) + __ldg(&bf2[d]);
    const float b_g = __ldg(&bg1[d]) + __ldg(&bg2[d]);
    const float b_o = __ldg(&bo1[d]) + __ldg(&bo2[d]);

    const int nb = gridDim.x;
    const int t0 = (int)((long long)blockIdx.x       * T_STEPS / nb);
    const int t1 = (int)((long long)(blockIdx.x + 1) * T_STEPS / nb);

    for (int t = t0; t < t1; t++) {
        const float* xr = x + (size_t)t * XW;
        float ai = b_i;
#pragma unroll
        for (int s = 0; s < S; s++) ai = fmaf(__ldg(&xr[DYN + s]), wi[s], ai);
        float af = b_f, ag = b_g, ao = b_o;
#pragma unroll
        for (int k = 0; k < DYN; k++) {
            float xv = __ldg(&xr[k]);
            af = fmaf(xv, wf[k], af);
            ag = fmaf(xv, wg[k], ag);
            ao = fmaf(xv, wo[k], ao);
        }
        size_t idx = (size_t)t * H + d;
        g_gi[idx] = sigmoid_fast(ai);
        g_xf[idx] = af;
        g_xg[idx] = ag;
        g_xo[idx] = ao;
    }
}

// ---------------- the sequential scan: persistent, chip-wide -----------------
// 128 CTAs x 4 warps; warp owns one h-dim. Weights register-resident
// (48 floats/lane). Per step: read full h from L2, 3 dots + butterfly
// reduce, gates, write own h value + release per-dim stamp; consumers
// acquire-poll all 512 stamps.
__global__ void __launch_bounds__(128, 1) scan_kernel(
    const float* __restrict__ c0,
    const float* __restrict__ Wf2,
    const float* __restrict__ Wg2,
    const float* __restrict__ Wo2)
{
    const int warp = threadIdx.x >> 5;
    const int lane = threadIdx.x & 31;
    const int d    = blockIdx.x * WARPS_PER_CTA + warp;   // owned h-dim

    float wf[16], wg[16], wo[16];
#pragma unroll
    for (int j = 0; j < 16; j++) {
        int k = lane + 32 * j;
        wf[j] = __ldg(&Wf2[(size_t)d * H + k]);
        wg[j] = __ldg(&Wg2[(size_t)d * H + k]);
        wo[j] = __ldg(&Wo2[(size_t)d * H + k]);
    }

    float c = __ldg(&c0[d]);   // carried cell state (lane 0's copy is live)

    // prefetch gate inputs for t = 0 (lane 0 only uses them)
    float xi = 0.f, xf = 0.f, xg = 0.f, xo = 0.f;
    if (lane == 0) {
        xi = __ldg(&g_gi[d]); xf = __ldg(&g_xf[d]);
        xg = __ldg(&g_xg[d]); xo = __ldg(&g_xo[d]);
    }

    for (int t = 0; t < T_STEPS; t++) {
        if (t > 0) {
            // wait until every dim has published H_t (stamp >= t)
            for (;;) {
                int mn = 0x7fffffff;
#pragma unroll
                for (int j = 0; j < 16; j++) {
                    int f = acq_load(&g_flags[lane + 32 * j]);
                    mn = f < mn ? f : mn;
                }
                if (__all_sync(0xffffffffu, mn >= t)) break;
            }
        }

        const float* hb = g_hbuf[t & 1];
        float acf = 0.f, acg = 0.f, aco = 0.f;
#pragma unroll
        for (int j = 0; j < 16; j++) {
            float hv = __ldcg(&hb[lane + 32 * j]);
            acf = fmaf(wf[j], hv, acf);
            acg = fmaf(wg[j], hv, acg);
            aco = fmaf(wo[j], hv, aco);
        }
#pragma unroll
        for (int s = 16; s; s >>= 1) {
            acf += __shfl_xor_sync(0xffffffffu, acf, s);
            acg += __shfl_xor_sync(0xffffffffu, acg, s);
            aco += __shfl_xor_sync(0xffffffffu, aco, s);
        }

        if (lane == 0) {
            float f = sigmoid_fast(xf + acf);
            float g = tanh_fast(xg + acg);
            float o = sigmoid_fast(xo + aco);
            c = fmaf(f, c, xi * g);
            float hn = o * tanh_fast(c);

            g_hall[(size_t)t * H + d] = hn;        // for output projection
            st_cg(&g_hbuf[(t + 1) & 1][d], hn);    // publish H_{t+1}
            rel_store(&g_flags[d], t + 1);         // stamp after data

            if (t + 1 < T_STEPS) {                 // prefetch next gate inputs
                size_t idx = (size_t)(t + 1) * H + d;
                xi = __ldg(&g_gi[idx]); xf = __ldg(&g_xf[idx]);
                xg = __ldg(&g_xg[idx]); xo = __ldg(&g_xo[idx]);
            }
        }
    }
}

// ---------------- epilogue: out[t] = h_all[t] . Wl + bl ----------------------
__global__ void __launch_bounds__(256) proj_kernel(
    const float* __restrict__ Wl, const float* __restrict__ bl,
    float* __restrict__ out)
{
    const int warp = threadIdx.x >> 5;
    const int lane = threadIdx.x & 31;
    const int t = blockIdx.x * 8 + warp;
    float acc = 0.f;
#pragma unroll
    for (int j = 0; j < 16; j++) {
        int k = lane + 32 * j;
        acc = fmaf(g_hall[(size_t)t * H + k], __ldg(&Wl[k]), acc);
    }
#pragma unroll
    for (int s = 16; s; s >>= 1) acc += __shfl_xor_sync(0xffffffffu, acc, s);
    if (lane == 0) out[t] = acc + __ldg(&bl[0]);
}

// ---------------- launch -----------------------------------------------------
extern "C" void kernel_launch(void* const* d_in, const int* in_sizes, int n_in,
                              void* d_out, int out_size)
{
    const float* x   = (const float*)d_in[0];
    const float* h0  = (const float*)d_in[1];
    const float* c0  = (const float*)d_in[2];
    const float* Wi  = (const float*)d_in[3];
    const float* bi  = (const float*)d_in[4];
    const float* Wf1 = (const float*)d_in[5];
    const float* bf1 = (const float*)d_in[6];
    const float* Wf2 = (const float*)d_in[7];
    const float* bf2 = (const float*)d_in[8];
    const float* Wg1 = (const float*)d_in[9];
    const float* bg1 = (const float*)d_in[10];
    const float* Wg2 = (const float*)d_in[11];
    const float* bg2 = (const float*)d_in[12];
    const float* Wo1 = (const float*)d_in[13];
    const float* bo1 = (const float*)d_in[14];
    const float* Wo2 = (const float*)d_in[15];
    const float* bo2 = (const float*)d_in[16];
    const float* Wl  = (const float*)d_in[17];
    const float* bl  = (const float*)d_in[18];
    float* out = (float*)d_out;

    init_kernel<<<1, 512>>>(h0);
    pre_kernel<<<148, 512>>>(x, Wi, bi, Wf1, bf1, bf2,
                             Wg1, bg1, bg2, Wo1, bo1, bo2);
    scan_kernel<<<NCTA, 32 * WARPS_PER_CTA>>>(c0, Wf2, Wg2, Wo2);
    proj_kernel<<<T_STEPS / 8, 256>>>(Wl, bl, out);
}

// round 3
// speedup vs baseline: 5.5876x; 5.5876x over previous
#include <cuda_runtime.h>
#include <cstdint>

#define T_STEPS 16384
#define H       512
#define DYN     16
#define S       32
#define XW      (DYN + S)

#define NCTA          128
#define WARPS_PER_CTA 4
#define CTA_THREADS   (32 * WARPS_PER_CTA)

// ---------------- static device scratch (allocation-free rule) ----------------
__device__ float g_hbuf[2][H];                  // double-buffered hidden state
__device__ unsigned int g_count;                // monotonic CTA-arrival counter
__device__ float g_hall[(size_t)T_STEPS * H];   // 32 MB
__device__ float g_gi [(size_t)T_STEPS * H];    // sigmoid(input gate)
__device__ float g_xf [(size_t)T_STEPS * H];
__device__ float g_xg [(size_t)T_STEPS * H];
__device__ float g_xo [(size_t)T_STEPS * H];

// ---------------- helpers ----------------
__device__ __forceinline__ float sigmoid_fast(float x) {
    return __fdividef(1.0f, 1.0f + __expf(-x));
}
__device__ __forceinline__ float tanh_fast(float x) {
    float ax = fabsf(x);
    float e  = __expf(-2.0f * ax);
    float r  = __fdividef(1.0f - e, 1.0f + e);
    return copysignf(r, x);
}
__device__ __forceinline__ unsigned int acq_load(const unsigned int* p) {
    unsigned int v;
    asm volatile("ld.acquire.gpu.global.u32 %0, [%1];" : "=r"(v) : "l"(p) : "memory");
    return v;
}
__device__ __forceinline__ void red_release_add(unsigned int* p, unsigned int v) {
    asm volatile("red.release.gpu.global.add.u32 [%0], %1;" :: "l"(p), "r"(v) : "memory");
}
__device__ __forceinline__ void st_cg(float* p, float v) {
    asm volatile("st.global.cg.f32 [%0], %1;" :: "l"(p), "f"(v) : "memory");
}
__device__ __forceinline__ float4 ldcg4(const float4* p) {
    float4 v;
    asm volatile("ld.global.cg.v4.f32 {%0,%1,%2,%3}, [%4];"
                 : "=f"(v.x), "=f"(v.y), "=f"(v.z), "=f"(v.w) : "l"(p) : "memory");
    return v;
}

// ---------------- init: reset state each launch (graph replay safe) ----------
__global__ void init_kernel(const float* __restrict__ h0) {
    int i = threadIdx.x;            // 512 threads
    g_hbuf[0][i] = h0[i];
    if (i == 0) g_count = 0u;
}

// ---------------- prologue: gate pre-activations, parallel over T ------------
__global__ void __launch_bounds__(512) pre_kernel(
    const float* __restrict__ x,
    const float* __restrict__ Wi,  const float* __restrict__ bi,
    const float* __restrict__ Wf1, const float* __restrict__ bf1, const float* __restrict__ bf2,
    const float* __restrict__ Wg1, const float* __restrict__ bg1, const float* __restrict__ bg2,
    const float* __restrict__ Wo1, const float* __restrict__ bo1, const float* __restrict__ bo2)
{
    const int d = threadIdx.x;      // one h-dim per thread
    float wi[S], wf[DYN], wg[DYN], wo[DYN];
#pragma unroll
    for (int s = 0; s < S; s++)   wi[s] = __ldg(&Wi[d * S + s]);
#pragma unroll
    for (int k = 0; k < DYN; k++) {
        wf[k] = __ldg(&Wf1[d * DYN + k]);
        wg[k] = __ldg(&Wg1[d * DYN + k]);
        wo[k] = __ldg(&Wo1[d * DYN + k]);
    }
    const float b_i = __ldg(&bi[d]);
    const float b_f = __ldg(&bf1[d]) + __ldg(&bf2[d]);
    const float b_g = __ldg(&bg1[d]) + __ldg(&bg2[d]);
    const float b_o = __ldg(&bo1[d]) + __ldg(&bo2[d]);

    const int nb = gridDim.x;
    const int t0 = (int)((long long)blockIdx.x       * T_STEPS / nb);
    const int t1 = (int)((long long)(blockIdx.x + 1) * T_STEPS / nb);

    for (int t = t0; t < t1; t++) {
        const float* xr = x + (size_t)t * XW;
        float ai = b_i;
#pragma unroll
        for (int s = 0; s < S; s++) ai = fmaf(__ldg(&xr[DYN + s]), wi[s], ai);
        float af = b_f, ag = b_g, ao = b_o;
#pragma unroll
        for (int k = 0; k < DYN; k++) {
            float xv = __ldg(&xr[k]);
            af = fmaf(xv, wf[k], af);
            ag = fmaf(xv, wg[k], ag);
            ao = fmaf(xv, wo[k], ao);
        }
        size_t idx = (size_t)t * H + d;
        g_gi[idx] = sigmoid_fast(ai);
        g_xf[idx] = af;
        g_xg[idx] = ag;
        g_xo[idx] = ao;
    }
}

// ---------------- the sequential scan: persistent, chip-wide -----------------
// 128 CTAs x 4 warps; each warp owns one h-dim. Per step:
//   tid0 polls single global counter (>= 128*t) -> __syncthreads fanout
//   CTA cooperatively stages h_t (2KB) into smem via float4 ld.cg
//   each warp: 3 dot products from smem, butterfly reduce, gates
//   lane0 publishes h_{t+1} (st.cg to alternate buffer) + g_hall
//   __syncthreads, tid0 does one red.release(+1) on the counter
__global__ void __launch_bounds__(CTA_THREADS, 1) scan_kernel(
    const float* __restrict__ c0,
    const float* __restrict__ Wf2,
    const float* __restrict__ Wg2,
    const float* __restrict__ Wo2)
{
    __shared__ float sh[H];

    const int tid  = threadIdx.x;
    const int warp = tid >> 5;
    const int lane = tid & 31;
    const int d    = blockIdx.x * WARPS_PER_CTA + warp;   // owned h-dim

    float wf[16], wg[16], wo[16];
#pragma unroll
    for (int j = 0; j < 16; j++) {
        int k = lane + 32 * j;
        wf[j] = __ldg(&Wf2[(size_t)d * H + k]);
        wg[j] = __ldg(&Wg2[(size_t)d * H + k]);
        wo[j] = __ldg(&Wo2[(size_t)d * H + k]);
    }

    float c = __ldg(&c0[d]);   // carried cell state (redundant across lanes)

    // gate inputs for t = 0 (broadcast loads, same addr across lanes)
    float xi = __ldg(&g_gi[d]);
    float xf = __ldg(&g_xf[d]);
    float xg = __ldg(&g_xg[d]);
    float xo = __ldg(&g_xo[d]);

    for (int t = 0; t < T_STEPS; t++) {
        if (t > 0) {
            if (tid == 0) {
                const unsigned int target = (unsigned int)NCTA * (unsigned int)t;
                while (acq_load(&g_count) < target) { }
            }
            __syncthreads();
        }

        // stage h_t into shared memory: 128 threads x float4
        {
            const float4* hb4 = (const float4*)g_hbuf[t & 1];
            float4 v = ldcg4(&hb4[tid]);
            *((float4*)&sh[tid * 4]) = v;
        }
        __syncthreads();

        float acf = 0.f, acg = 0.f, aco = 0.f;
#pragma unroll
        for (int j = 0; j < 16; j++) {
            float hv = sh[lane + 32 * j];
            acf = fmaf(wf[j], hv, acf);
            acg = fmaf(wg[j], hv, acg);
            aco = fmaf(wo[j], hv, aco);
        }
#pragma unroll
        for (int s = 16; s; s >>= 1) {
            acf += __shfl_xor_sync(0xffffffffu, acf, s);
            acg += __shfl_xor_sync(0xffffffffu, acg, s);
            aco += __shfl_xor_sync(0xffffffffu, aco, s);
        }

        // all lanes compute gates redundantly (no divergence on the math)
        float f = sigmoid_fast(xf + acf);
        float g = tanh_fast(xg + acg);
        float o = sigmoid_fast(xo + aco);
        c = fmaf(f, c, xi * g);
        float hn = o * tanh_fast(c);

        if (lane == 0) {
            g_hall[(size_t)t * H + d] = hn;        // for output projection
            st_cg(&g_hbuf[(t + 1) & 1][d], hn);    // publish h_{t+1}
        }

        // prefetch next step's gate inputs (independent of the sync)
        if (t + 1 < T_STEPS) {
            size_t idx = (size_t)(t + 1) * H + d;
            xi = __ldg(&g_gi[idx]); xf = __ldg(&g_xf[idx]);
            xg = __ldg(&g_xg[idx]); xo = __ldg(&g_xo[idx]);
        }

        __syncthreads();                            // all 4 dims published
        if (tid == 0) red_release_add(&g_count, 1u);
    }
}

// ---------------- epilogue: out[t] = h_all[t] . Wl + bl ----------------------
__global__ void __launch_bounds__(256) proj_kernel(
    const float* __restrict__ Wl, const float* __restrict__ bl,
    float* __restrict__ out)
{
    const int warp = threadIdx.x >> 5;
    const int lane = threadIdx.x & 31;
    const int t = blockIdx.x * 8 + warp;
    float acc = 0.f;
#pragma unroll
    for (int j = 0; j < 16; j++) {
        int k = lane + 32 * j;
        acc = fmaf(g_hall[(size_t)t * H + k], __ldg(&Wl[k]), acc);
    }
#pragma unroll
    for (int s = 16; s; s >>= 1) acc += __shfl_xor_sync(0xffffffffu, acc, s);
    if (lane == 0) out[t] = acc + __ldg(&bl[0]);
}

// ---------------- launch -----------------------------------------------------
extern "C" void kernel_launch(void* const* d_in, const int* in_sizes, int n_in,
                              void* d_out, int out_size)
{
    const float* x   = (const float*)d_in[0];
    const float* h0  = (const float*)d_in[1];
    const float* c0  = (const float*)d_in[2];
    const float* Wi  = (const float*)d_in[3];
    const float* bi  = (const float*)d_in[4];
    const float* Wf1 = (const float*)d_in[5];
    const float* bf1 = (const float*)d_in[6];
    const float* Wf2 = (const float*)d_in[7];
    const float* bf2 = (const float*)d_in[8];
    const float* Wg1 = (const float*)d_in[9];
    const float* bg1 = (const float*)d_in[10];
    const float* Wg2 = (const float*)d_in[11];
    const float* bg2 = (const float*)d_in[12];
    const float* Wo1 = (const float*)d_in[13];
    const float* bo1 = (const float*)d_in[14];
    const float* Wo2 = (const float*)d_in[15];
    const float* bo2 = (const float*)d_in[16];
    const float* Wl  = (const float*)d_in[17];
    const float* bl  = (const float*)d_in[18];
    float* out = (float*)d_out;

    init_kernel<<<1, 512>>>(h0);
    pre_kernel<<<148, 512>>>(x, Wi, bi, Wf1, bf1, bf2,
                             Wg1, bg1, bg2, Wo1, bo1, bo2);
    scan_kernel<<<NCTA, CTA_THREADS>>>(c0, Wf2, Wg2, Wo2);
    proj_kernel<<<T_STEPS / 8, 256>>>(Wl, bl, out);
}